// round 16
// baseline (speedup 1.0000x reference)
#include <cuda_runtime.h>
#include <cuda_bf16.h>
#include <cstdint>

#define Hh 8
#define Dd 64
#define Ss 32
#define Bg 8
#define MAXN 30720
#define CHUNK 128
#define PADK 40   // bf16 row stride in smem (80B) -> conflict-free ldmatrix

// ---------------- scratch (static device globals; no allocation) ----------------
__device__ float g_cat[MAXN * 768];         // [N, 768]: cols 0..511 fx, 512..767 logits (fp32)
__device__ __nv_bfloat16 g_xh[MAXN * 256];  // x bf16 hi
__device__ __nv_bfloat16 g_xl[MAXN * 256];  // x bf16 lo
__device__ __nv_bfloat16 g_bWh[768 * 256];  // fused weight bf16 hi [n=768][k=256]
__device__ __nv_bfloat16 g_bWl[768 * 256];  // fused weight bf16 lo
__device__ __nv_bfloat16 g_wh[MAXN * 256];  // softmaxed w bf16 hi [n][k=256]
__device__ __nv_bfloat16 g_wl[MAXN * 256];  // softmaxed w bf16 lo
__device__ float g_bigb[768];
__device__ float g_st[Bg * Hh * Ss * Dd];   // slice_token accum  [B,H,S,D] = 131072 floats
__device__ float g_sn[Bg * Hh * Ss];        // slice_norm accum   [B,H,S]   = 2048 floats
__device__ float g_ot[Bg * Hh * Ss * Dd];   // out_tok            [B,H,S,D]
__device__ __nv_bfloat16 g_m1h[Bg * 256 * 256]; // M1 transposed bf16 hi [b][j=256][hs=256]
__device__ __nv_bfloat16 g_m1l[Bg * 256 * 256]; // M1 transposed bf16 lo

__device__ __forceinline__ uint32_t smem_u32(const void* p) {
    uint32_t a;
    asm("{ .reg .u64 t; cvta.to.shared.u64 t, %1; cvt.u32.u64 %0, t; }" : "=r"(a) : "l"(p));
    return a;
}
__device__ __forceinline__ uint16_t bfbits(float f) {
    return __bfloat16_as_ushort(__float2bfloat16(f));
}
__device__ __forceinline__ void ldsm_x4(uint32_t* r, uint32_t addr) {
    asm volatile("ldmatrix.sync.aligned.m8n8.x4.shared.b16 {%0,%1,%2,%3}, [%4];"
        : "=r"(r[0]), "=r"(r[1]), "=r"(r[2]), "=r"(r[3]) : "r"(addr));
}
__device__ __forceinline__ void mma_bf16(float* d, const uint32_t* a, const uint32_t* b) {
    asm volatile("mma.sync.aligned.m16n8k16.row.col.f32.bf16.bf16.f32 "
        "{%0,%1,%2,%3}, {%4,%5,%6,%7}, {%8,%9}, {%0,%1,%2,%3};"
        : "+f"(d[0]), "+f"(d[1]), "+f"(d[2]), "+f"(d[3])
        : "r"(a[0]), "r"(a[1]), "r"(a[2]), "r"(a[3]), "r"(b[0]), "r"(b[1]));
}
__device__ __forceinline__ void split4(float4 v, uint32_t& h0, uint32_t& h1,
                                       uint32_t& l0, uint32_t& l1) {
    uint16_t hx = bfbits(v.x), hy = bfbits(v.y), hz = bfbits(v.z), hw = bfbits(v.w);
    h0 = (uint32_t)hx | ((uint32_t)hy << 16);
    h1 = (uint32_t)hz | ((uint32_t)hw << 16);
    float lx = v.x - __bfloat162float(__ushort_as_bfloat16(hx));
    float ly = v.y - __bfloat162float(__ushort_as_bfloat16(hy));
    float lz = v.z - __bfloat162float(__ushort_as_bfloat16(hz));
    float lw = v.w - __bfloat162float(__ushort_as_bfloat16(hw));
    l0 = (uint32_t)bfbits(lx) | ((uint32_t)bfbits(ly) << 16);
    l1 = (uint32_t)bfbits(lz) | ((uint32_t)bfbits(lw) << 16);
}
__device__ __forceinline__ void split_store(float v, __nv_bfloat16* ph, __nv_bfloat16* pl) {
    __nv_bfloat16 h = __float2bfloat16(v);
    *ph = h;
    *pl = __float2bfloat16(v - __bfloat162float(h));
}

// -------- prep: fused weight -> bf16 hi/lo; also zero scatter accumulators -----
__global__ void prep_weights(const float* __restrict__ W_fx, const float* __restrict__ b_fx,
                             const float* __restrict__ W_x, const float* __restrict__ b_x,
                             const float* __restrict__ W_slice, const float* __restrict__ b_slice) {
    int k = blockIdx.x;          // 0..255
    int t = threadIdx.x;         // 0..255
    // folded zeroing: g_st = 131072 floats -> every block zeroes 512 of them
    g_st[k * 512 + t] = 0.f;
    g_st[k * 512 + 256 + t] = 0.f;
    if (k < 8) g_sn[k * 256 + t] = 0.f;    // g_sn = 2048 floats

    for (int c = t; c < 512; c += 256)
        split_store(W_fx[k * 512 + c], &g_bWh[(size_t)c * 256 + k], &g_bWl[(size_t)c * 256 + k]);
    {
        int h = t >> 5, s = t & 31;
        float a = 0.f;
        #pragma unroll
        for (int d = 0; d < 64; d++)
            a += W_x[k * 512 + h * 64 + d] * W_slice[d * 32 + s];
        split_store(a, &g_bWh[(size_t)(512 + t) * 256 + k], &g_bWl[(size_t)(512 + t) * 256 + k]);
    }
    if (k == 0) {
        for (int c = t; c < 512; c += 256) g_bigb[c] = b_fx[c];
        int h = t >> 5, s = t & 31;
        float bb = b_slice[s];
        #pragma unroll
        for (int d = 0; d < 64; d++)
            bb += b_x[h * 64 + d] * W_slice[d * 32 + s];
        g_bigb[512 + t] = bb;
    }
}

// ---------------- pre-pass: x fp32 -> bf16 hi/lo (paid once, not 6x) -----------
__global__ void convert_x(const float* __restrict__ x, int total4) {
    int i = blockIdx.x * blockDim.x + threadIdx.x;
    if (i >= total4) return;
    float4 v = ((const float4*)x)[i];
    uint32_t h0, h1, l0, l1;
    split4(v, h0, h1, l0, l1);
    ((uint2*)g_xh)[i] = make_uint2(h0, h1);
    ((uint2*)g_xl)[i] = make_uint2(l0, l1);
}

// ========== split-bf16 HMMA fused GEMM: g_cat = x @ bigW + bias ===============
// Block tile 128x128, K=256 in 8 chunks of 32. 8 warps = 4(m) x 2(n), warp 32x64.
__global__ __launch_bounds__(256, 2) void fused_gemm_mma(int M) {
    __shared__ __align__(16) uint32_t Ahi[128 * PADK / 2];
    __shared__ __align__(16) uint32_t Alo[128 * PADK / 2];
    __shared__ __align__(16) uint32_t Bhi[128 * PADK / 2];
    __shared__ __align__(16) uint32_t Blo[128 * PADK / 2];

    int tid = threadIdx.x, wid = tid >> 5, lane = tid & 31;
    int bx = blockIdx.x, by = blockIdx.y;
    int row0 = by * 128, n0 = bx * 128;
    int warp_m = (wid & 3) * 32, warp_n = (wid >> 2) * 64;

    float acc[2][8][4];
    #pragma unroll
    for (int mi = 0; mi < 2; mi++)
        #pragma unroll
        for (int ni = 0; ni < 8; ni++)
            #pragma unroll
            for (int j = 0; j < 4; j++) acc[mi][ni][j] = 0.f;

    int a_row = ((lane >> 3) & 1) * 8 + (lane & 7);
    int a_col = (lane >> 4) * 8;
    int b_row = ((lane >> 4) & 1) * 8 + (lane & 7);
    int b_col = ((lane >> 3) & 1) * 8;

    uint32_t sAhi = smem_u32(Ahi), sAlo = smem_u32(Alo);
    uint32_t sBhi = smem_u32(Bhi), sBlo = smem_u32(Blo);

    int lrow = tid >> 1;                 // 0..127
    int lc0 = (tid & 1) * 16;            // 0 or 16

    for (int c = 0; c < 8; c++) {
        int k0 = c * 32;
        // ---- A chunk 128x32: direct bf16 hi/lo loads ----
        {
            int gr = row0 + lrow;
            uint32_t* dh = &Ahi[(lrow * PADK + lc0) >> 1];
            uint32_t* dl = &Alo[(lrow * PADK + lc0) >> 1];
            if (gr < M) {
                const uint4* sh = (const uint4*)&g_xh[(size_t)gr * 256 + k0 + lc0];
                const uint4* sl = (const uint4*)&g_xl[(size_t)gr * 256 + k0 + lc0];
                uint4 h0 = sh[0], h1 = sh[1], l0 = sl[0], l1 = sl[1];
                dh[0] = h0.x; dh[1] = h0.y; dh[2] = h0.z; dh[3] = h0.w;
                dh[4] = h1.x; dh[5] = h1.y; dh[6] = h1.z; dh[7] = h1.w;
                dl[0] = l0.x; dl[1] = l0.y; dl[2] = l0.z; dl[3] = l0.w;
                dl[4] = l1.x; dl[5] = l1.y; dl[6] = l1.z; dl[7] = l1.w;
            } else {
                #pragma unroll
                for (int i = 0; i < 8; i++) { dh[i] = 0u; dl[i] = 0u; }
            }
        }
        // ---- B chunk 128x32: direct bf16 hi/lo loads ----
        {
            const uint4* sh = (const uint4*)&g_bWh[(size_t)(n0 + lrow) * 256 + k0 + lc0];
            const uint4* sl = (const uint4*)&g_bWl[(size_t)(n0 + lrow) * 256 + k0 + lc0];
            uint32_t* dh = &Bhi[(lrow * PADK + lc0) >> 1];
            uint32_t* dl = &Blo[(lrow * PADK + lc0) >> 1];
            uint4 h0 = sh[0], h1 = sh[1], l0 = sl[0], l1 = sl[1];
            dh[0] = h0.x; dh[1] = h0.y; dh[2] = h0.z; dh[3] = h0.w;
            dh[4] = h1.x; dh[5] = h1.y; dh[6] = h1.z; dh[7] = h1.w;
            dl[0] = l0.x; dl[1] = l0.y; dl[2] = l0.z; dl[3] = l0.w;
            dl[4] = l1.x; dl[5] = l1.y; dl[6] = l1.z; dl[7] = l1.w;
        }
        __syncthreads();

        #pragma unroll
        for (int p = 0; p < 3; p++) {
            uint32_t sA = (p == 2) ? sAlo : sAhi;
            uint32_t sB = (p == 1) ? sBlo : sBhi;
            #pragma unroll
            for (int ks = 0; ks < 2; ks++) {
                int kb = ks * 16;
                uint32_t af[2][4];
                #pragma unroll
                for (int mi = 0; mi < 2; mi++)
                    ldsm_x4(af[mi], sA + ((warp_m + mi * 16 + a_row) * PADK + kb + a_col) * 2);
                uint32_t bfr[8][2];
                #pragma unroll
                for (int nj = 0; nj < 4; nj++) {
                    uint32_t r[4];
                    ldsm_x4(r, sB + ((warp_n + nj * 16 + b_row) * PADK + kb + b_col) * 2);
                    bfr[nj * 2][0] = r[0]; bfr[nj * 2][1] = r[1];
                    bfr[nj * 2 + 1][0] = r[2]; bfr[nj * 2 + 1][1] = r[3];
                }
                #pragma unroll
                for (int mi = 0; mi < 2; mi++)
                    #pragma unroll
                    for (int ni = 0; ni < 8; ni++)
                        mma_bf16(acc[mi][ni], af[mi], bfr[ni]);
            }
        }
        __syncthreads();
    }

    // ---- epilogue: add bias, store fp32 to g_cat ----
    int r_in = lane >> 2, c_in = (lane & 3) * 2;
    #pragma unroll
    for (int mi = 0; mi < 2; mi++) {
        #pragma unroll
        for (int ni = 0; ni < 8; ni++) {
            int gc = n0 + warp_n + ni * 8 + c_in;
            float b0 = g_bigb[gc], b1 = g_bigb[gc + 1];
            int gr0 = row0 + warp_m + mi * 16 + r_in;
            if (gr0 < M) {
                float2 o = make_float2(acc[mi][ni][0] + b0, acc[mi][ni][1] + b1);
                *(float2*)&g_cat[(size_t)gr0 * 768 + gc] = o;
            }
            int gr1 = gr0 + 8;
            if (gr1 < M) {
                float2 o = make_float2(acc[mi][ni][2] + b0, acc[mi][ni][3] + b1);
                *(float2*)&g_cat[(size_t)gr1 * 768 + gc] = o;
            }
        }
    }
}

// ------ fused softmax + scatter: warp-per-h, lane-per-s (S=32=warp width) ------
// reads raw logits, softmaxes across the warp, emits bf16 w, accumulates pooling.
__global__ void scatter_kernel(const int* __restrict__ batch,
                               const float* __restrict__ temp, int N) {
    int h = threadIdx.x >> 5;
    int lane = threadIdx.x & 31;
    int start = blockIdx.x * CHUNK;
    int end = min(start + CHUNK, N);
    float invt = 1.0f / temp[h];

    float acc[64];
    #pragma unroll
    for (int d = 0; d < 64; d++) acc[d] = 0.f;
    float accn = 0.f;
    int cur_b = __ldg(&batch[start]);

    for (int n = start; n < end; n++) {
        int bn = __ldg(&batch[n]);
        if (bn != cur_b) {
            float* st = g_st + (((size_t)cur_b * 8 + h) * 32 + lane) * 64;
            #pragma unroll
            for (int d = 0; d < 64; d++) { atomicAdd(&st[d], acc[d]); acc[d] = 0.f; }
            atomicAdd(&g_sn[(cur_b * 8 + h) * 32 + lane], accn);
            accn = 0.f;
            cur_b = bn;
        }
        const float* row = &g_cat[(size_t)n * 768];
        // inline tempered softmax over the 32 lanes (= slices)
        float lg = row[512 + h * 32 + lane] * invt;
        float m = lg;
        #pragma unroll
        for (int o = 16; o; o >>= 1) m = fmaxf(m, __shfl_xor_sync(0xffffffffu, m, o));
        float e = __expf(lg - m);
        float s = e;
        #pragma unroll
        for (int o = 16; o; o >>= 1) s += __shfl_xor_sync(0xffffffffu, s, o);
        float wv = e / s;
        size_t widx = (size_t)n * 256 + h * 32 + lane;
        split_store(wv, &g_wh[widx], &g_wl[widx]);

        float f0 = row[h * 64 + lane];
        float f1 = row[h * 64 + 32 + lane];
        accn += wv;
        #pragma unroll
        for (int d = 0; d < 32; d++) {
            acc[d]      += wv * __shfl_sync(0xffffffffu, f0, d);
            acc[d + 32] += wv * __shfl_sync(0xffffffffu, f1, d);
        }
    }
    float* st = g_st + (((size_t)cur_b * 8 + h) * 32 + lane) * 64;
    #pragma unroll
    for (int d = 0; d < 64; d++) atomicAdd(&st[d], acc[d]);
    atomicAdd(&g_sn[(cur_b * 8 + h) * 32 + lane], accn);
}

// ---------------- tiny attention over slice tokens, one block per (b,h) --------
__global__ void attention_kernel(const float* __restrict__ W_q, const float* __restrict__ W_k,
                                 const float* __restrict__ W_v) {
    int bh = blockIdx.x;
    __shared__ float st[32 * 64];
    __shared__ float q[32 * 64];
    __shared__ float kT[64 * 33];
    __shared__ float v[32 * 64];
    __shared__ float attn[32 * 32];
    int tid = threadIdx.x;
    const float* base = g_st + (size_t)bh * 2048;
    const float* nrm = g_sn + bh * 32;

    for (int i = tid; i < 2048; i += 256) {
        int s = i >> 6;
        st[i] = base[i] / (nrm[s] + 1e-5f);
    }
    __syncthreads();
    for (int i = tid; i < 2048; i += 256) {
        int s = i >> 6, e = i & 63;
        float aq = 0.f, ak = 0.f, av = 0.f;
        #pragma unroll
        for (int d = 0; d < 64; d++) {
            float sv = st[s * 64 + d];
            aq += sv * W_q[d * 64 + e];
            ak += sv * W_k[d * 64 + e];
            av += sv * W_v[d * 64 + e];
        }
        q[i] = aq; kT[e * 33 + s] = ak; v[i] = av;
    }
    __syncthreads();
    for (int i = tid; i < 1024; i += 256) {
        int s = i >> 5, t = i & 31;
        float a = 0.f;
        #pragma unroll
        for (int d = 0; d < 64; d++) a += q[s * 64 + d] * kT[d * 33 + t];
        attn[i] = a * 0.125f;
    }
    __syncthreads();
    int warp = tid >> 5, lane = tid & 31;
    for (int r = warp; r < 32; r += 8) {
        float val = attn[r * 32 + lane];
        float m = val;
        #pragma unroll
        for (int o = 16; o; o >>= 1) m = fmaxf(m, __shfl_xor_sync(0xffffffffu, m, o));
        float e = __expf(val - m);
        float ssum = e;
        #pragma unroll
        for (int o = 16; o; o >>= 1) ssum += __shfl_xor_sync(0xffffffffu, ssum, o);
        attn[r * 32 + lane] = e / ssum;
    }
    __syncthreads();
    float* ob = g_ot + (size_t)bh * 2048;
    for (int i = tid; i < 2048; i += 256) {
        int s = i >> 6, d = i & 63;
        float a = 0.f;
        #pragma unroll
        for (int t = 0; t < 32; t++) a += attn[s * 32 + t] * v[t * 64 + d];
        ob[i] = a;
    }
}

// --------- fold out_tok with W_out -> M1 TRANSPOSED bf16 hi/lo [b][j][hs] ------
__global__ void build_m1(const float* __restrict__ W_out) {
    int bh = blockIdx.x;
    int h = bh & 7, b = bh >> 3;
    __shared__ float ot[2048];
    int tid = threadIdx.x;
    for (int i = tid; i < 2048; i += 256) ot[i] = g_ot[(size_t)bh * 2048 + i];
    __syncthreads();
    for (int i = tid; i < 8192; i += 256) {
        int s = i >> 8, j = i & 255;
        float a = 0.f;
        #pragma unroll
        for (int d = 0; d < 64; d++)
            a += ot[s * 64 + d] * W_out[(h * 64 + d) * 256 + j];
        size_t idx = ((size_t)b * 256 + j) * 256 + (h * 32 + s);
        split_store(a, &g_m1h[idx], &g_m1l[idx]);
    }
}

// ===== final: out[n,:] = w[n,:] @ M1[batch[n]] + b_out (split-bf16 HMMA) ======
__global__ __launch_bounds__(256, 2) void final_gemm_mma(
    int M, const int* __restrict__ batch,
    const float* __restrict__ bias, float* __restrict__ C)
{
    __shared__ __align__(16) uint32_t Ahi[128 * PADK / 2];
    __shared__ __align__(16) uint32_t Alo[128 * PADK / 2];
    __shared__ __align__(16) uint32_t Bhi[128 * PADK / 2];
    __shared__ __align__(16) uint32_t Blo[128 * PADK / 2];
    __shared__ int sb[128];

    int tid = threadIdx.x, wid = tid >> 5, lane = tid & 31;
    int bx = blockIdx.x, by = blockIdx.y;
    int row0 = by * 128, n0 = bx * 128;
    int rows = min(128, M - row0);
    int warp_m = (wid & 3) * 32, warp_n = (wid >> 2) * 64;

    for (int i = tid; i < 128; i += 256) sb[i] = (i < rows) ? batch[row0 + i] : -1;
    __syncthreads();
    int b_first = sb[0], b_last = sb[rows - 1];

    int a_row = ((lane >> 3) & 1) * 8 + (lane & 7);
    int a_col = (lane >> 4) * 8;
    int b_row = ((lane >> 4) & 1) * 8 + (lane & 7);
    int b_col = ((lane >> 3) & 1) * 8;

    uint32_t sAhi = smem_u32(Ahi), sAlo = smem_u32(Alo);
    uint32_t sBhi = smem_u32(Bhi), sBlo = smem_u32(Blo);

    int lrow = tid >> 1;
    int lc0 = (tid & 1) * 16;
    int r_in = lane >> 2, c_in = (lane & 3) * 2;

    for (int bb = b_first; bb <= b_last; bb++) {
        float acc[2][8][4];
        #pragma unroll
        for (int mi = 0; mi < 2; mi++)
            #pragma unroll
            for (int ni = 0; ni < 8; ni++)
                #pragma unroll
                for (int j = 0; j < 4; j++) acc[mi][ni][j] = 0.f;

        const __nv_bfloat16* Bh = g_m1h + (size_t)bb * 65536;
        const __nv_bfloat16* Bl = g_m1l + (size_t)bb * 65536;

        for (int c = 0; c < 8; c++) {
            int k0 = c * 32;
            // ---- A chunk: w bf16 hi/lo [128 x 32] ----
            {
                int gr = row0 + lrow;
                uint32_t* dh = &Ahi[(lrow * PADK + lc0) >> 1];
                uint32_t* dl = &Alo[(lrow * PADK + lc0) >> 1];
                if (gr < M) {
                    const uint4* sh = (const uint4*)&g_wh[(size_t)gr * 256 + k0 + lc0];
                    const uint4* sl = (const uint4*)&g_wl[(size_t)gr * 256 + k0 + lc0];
                    uint4 h0 = sh[0], h1 = sh[1], l0 = sl[0], l1 = sl[1];
                    dh[0] = h0.x; dh[1] = h0.y; dh[2] = h0.z; dh[3] = h0.w;
                    dh[4] = h1.x; dh[5] = h1.y; dh[6] = h1.z; dh[7] = h1.w;
                    dl[0] = l0.x; dl[1] = l0.y; dl[2] = l0.z; dl[3] = l0.w;
                    dl[4] = l1.x; dl[5] = l1.y; dl[6] = l1.z; dl[7] = l1.w;
                } else {
                    #pragma unroll
                    for (int i = 0; i < 8; i++) { dh[i] = 0u; dl[i] = 0u; }
                }
            }
            // ---- B chunk: M1t bf16 hi/lo [128 x 32] ----
            {
                const uint4* sh = (const uint4*)&Bh[(size_t)(n0 + lrow) * 256 + k0 + lc0];
                const uint4* sl = (const uint4*)&Bl[(size_t)(n0 + lrow) * 256 + k0 + lc0];
                uint32_t* dh = &Bhi[(lrow * PADK + lc0) >> 1];
                uint32_t* dl = &Blo[(lrow * PADK + lc0) >> 1];
                uint4 h0 = sh[0], h1 = sh[1], l0 = sl[0], l1 = sl[1];
                dh[0] = h0.x; dh[1] = h0.y; dh[2] = h0.z; dh[3] = h0.w;
                dh[4] = h1.x; dh[5] = h1.y; dh[6] = h1.z; dh[7] = h1.w;
                dl[0] = l0.x; dl[1] = l0.y; dl[2] = l0.z; dl[3] = l0.w;
                dl[4] = l1.x; dl[5] = l1.y; dl[6] = l1.z; dl[7] = l1.w;
            }
            __syncthreads();

            #pragma unroll
            for (int p = 0; p < 3; p++) {
                uint32_t sA = (p == 2) ? sAlo : sAhi;
                uint32_t sB = (p == 1) ? sBlo : sBhi;
                #pragma unroll
                for (int ks = 0; ks < 2; ks++) {
                    int kb = ks * 16;
                    uint32_t af[2][4];
                    #pragma unroll
                    for (int mi = 0; mi < 2; mi++)
                        ldsm_x4(af[mi], sA + ((warp_m + mi * 16 + a_row) * PADK + kb + a_col) * 2);
                    uint32_t bfr[8][2];
                    #pragma unroll
                    for (int nj = 0; nj < 4; nj++) {
                        uint32_t r[4];
                        ldsm_x4(r, sB + ((warp_n + nj * 16 + b_row) * PADK + kb + b_col) * 2);
                        bfr[nj * 2][0] = r[0]; bfr[nj * 2][1] = r[1];
                        bfr[nj * 2 + 1][0] = r[2]; bfr[nj * 2 + 1][1] = r[3];
                    }
                    #pragma unroll
                    for (int mi = 0; mi < 2; mi++)
                        #pragma unroll
                        for (int ni = 0; ni < 8; ni++)
                            mma_bf16(acc[mi][ni], af[mi], bfr[ni]);
                }
            }
            __syncthreads();
        }

        // ---- epilogue: rows belonging to bb only ----
        #pragma unroll
        for (int mi = 0; mi < 2; mi++) {
            #pragma unroll
            for (int ni = 0; ni < 8; ni++) {
                int gc = n0 + warp_n + ni * 8 + c_in;
                float b0 = bias[gc], b1 = bias[gc + 1];
                int lr0 = warp_m + mi * 16 + r_in;
                int gr0 = row0 + lr0;
                if (gr0 < M && sb[lr0] == bb) {
                    float2 o = make_float2(acc[mi][ni][0] + b0, acc[mi][ni][1] + b1);
                    *(float2*)&C[(size_t)gr0 * 256 + gc] = o;
                }
                int lr1 = lr0 + 8;
                int gr1 = gr0 + 8;
                if (gr1 < M && sb[lr1] == bb) {
                    float2 o = make_float2(acc[mi][ni][2] + b0, acc[mi][ni][3] + b1);
                    *(float2*)&C[(size_t)gr1 * 256 + gc] = o;
                }
            }
        }
    }
}

// ---------------- launch ----------------
extern "C" void kernel_launch(void* const* d_in, const int* in_sizes, int n_in,
                              void* d_out, int out_size) {
    const float* x       = (const float*)d_in[0];
    const int*   batch   = (const int*)d_in[1];
    const float* W_fx    = (const float*)d_in[2];
    const float* b_fx    = (const float*)d_in[3];
    const float* W_x     = (const float*)d_in[4];
    const float* b_x     = (const float*)d_in[5];
    const float* W_slice = (const float*)d_in[6];
    const float* b_slice = (const float*)d_in[7];
    const float* gtemp   = (const float*)d_in[8];
    const float* W_q     = (const float*)d_in[9];
    const float* W_k     = (const float*)d_in[10];
    const float* W_v     = (const float*)d_in[11];
    const float* W_out   = (const float*)d_in[12];
    const float* b_out   = (const float*)d_in[13];
    float* out = (float*)d_out;

    int n = in_sizes[1];
    int rowBlocks = (n + 127) / 128;

    // 1. build fused weight bf16 hi/lo + bias; zero accumulators (full 131072+2048)
    prep_weights<<<256, 256>>>(W_fx, b_fx, W_x, b_x, W_slice, b_slice);
    // 2. pre-convert x to bf16 hi/lo (once, not per bx tile)
    convert_x<<<(n * 64 + 255) / 256, 256>>>(x, n * 64);
    // 3. split-bf16 HMMA fused GEMM: [fx | logits] = x @ bigW + bigb
    fused_gemm_mma<<<dim3(6, rowBlocks), 256>>>(n);
    // 4. fused softmax + scatter-add pooling (+ bf16 w emission)
    scatter_kernel<<<rowBlocks, 256>>>(batch, gtemp, n);
    // 5. tiny attention over slice tokens
    attention_kernel<<<64, 256>>>(W_q, W_k, W_v);
    // 6. fold out_tok with W_out -> transposed bf16 hi/lo M1
    build_m1<<<64, 256>>>(W_out);
    // 7. out = w @ M1[batch] + b_out   (split-bf16 HMMA)
    final_gemm_mma<<<dim3(2, rowBlocks), 256>>>(n, batch, b_out, out);
}

// round 17
// speedup vs baseline: 1.1312x; 1.1312x over previous
#include <cuda_runtime.h>
#include <cuda_bf16.h>
#include <cstdint>

#define Hh 8
#define Dd 64
#define Ss 32
#define Bg 8
#define MAXN 30720
#define CHUNK 128
#define PADK 40   // bf16 row stride in smem (80B) -> conflict-free ldmatrix

// ---------------- scratch (static device globals; no allocation) ----------------
__device__ float g_cat[MAXN * 768];         // [N, 768]: cols 0..511 fx, 512..767 w (fp32)
__device__ __nv_bfloat16 g_xh[MAXN * 256];  // x bf16 hi
__device__ __nv_bfloat16 g_xl[MAXN * 256];  // x bf16 lo
__device__ __nv_bfloat16 g_bWh[768 * 256];  // fused weight bf16 hi [n=768][k=256]
__device__ __nv_bfloat16 g_bWl[768 * 256];  // fused weight bf16 lo
__device__ __nv_bfloat16 g_wh[MAXN * 256];  // softmaxed w bf16 hi [n][k=256]
__device__ __nv_bfloat16 g_wl[MAXN * 256];  // softmaxed w bf16 lo
__device__ float g_bigb[768];
__device__ float g_st[Bg * Hh * Ss * Dd];   // slice_token accum  [B,H,S,D] = 131072 floats
__device__ float g_sn[Bg * Hh * Ss];        // slice_norm accum   [B,H,S]   = 2048 floats
__device__ float g_ot[Bg * Hh * Ss * Dd];   // out_tok            [B,H,S,D]
__device__ __nv_bfloat16 g_m1h[Bg * 256 * 256]; // M1 transposed bf16 hi [b][j=256][hs=256]
__device__ __nv_bfloat16 g_m1l[Bg * 256 * 256]; // M1 transposed bf16 lo

__device__ __forceinline__ uint32_t smem_u32(const void* p) {
    uint32_t a;
    asm("{ .reg .u64 t; cvta.to.shared.u64 t, %1; cvt.u32.u64 %0, t; }" : "=r"(a) : "l"(p));
    return a;
}
__device__ __forceinline__ uint16_t bfbits(float f) {
    return __bfloat16_as_ushort(__float2bfloat16(f));
}
__device__ __forceinline__ void ldsm_x4(uint32_t* r, uint32_t addr) {
    asm volatile("ldmatrix.sync.aligned.m8n8.x4.shared.b16 {%0,%1,%2,%3}, [%4];"
        : "=r"(r[0]), "=r"(r[1]), "=r"(r[2]), "=r"(r[3]) : "r"(addr));
}
__device__ __forceinline__ void mma_bf16(float* d, const uint32_t* a, const uint32_t* b) {
    asm volatile("mma.sync.aligned.m16n8k16.row.col.f32.bf16.bf16.f32 "
        "{%0,%1,%2,%3}, {%4,%5,%6,%7}, {%8,%9}, {%0,%1,%2,%3};"
        : "+f"(d[0]), "+f"(d[1]), "+f"(d[2]), "+f"(d[3])
        : "r"(a[0]), "r"(a[1]), "r"(a[2]), "r"(a[3]), "r"(b[0]), "r"(b[1]));
}
__device__ __forceinline__ void split4(float4 v, uint32_t& h0, uint32_t& h1,
                                       uint32_t& l0, uint32_t& l1) {
    uint16_t hx = bfbits(v.x), hy = bfbits(v.y), hz = bfbits(v.z), hw = bfbits(v.w);
    h0 = (uint32_t)hx | ((uint32_t)hy << 16);
    h1 = (uint32_t)hz | ((uint32_t)hw << 16);
    float lx = v.x - __bfloat162float(__ushort_as_bfloat16(hx));
    float ly = v.y - __bfloat162float(__ushort_as_bfloat16(hy));
    float lz = v.z - __bfloat162float(__ushort_as_bfloat16(hz));
    float lw = v.w - __bfloat162float(__ushort_as_bfloat16(hw));
    l0 = (uint32_t)bfbits(lx) | ((uint32_t)bfbits(ly) << 16);
    l1 = (uint32_t)bfbits(lz) | ((uint32_t)bfbits(lw) << 16);
}
__device__ __forceinline__ void split_store(float v, __nv_bfloat16* ph, __nv_bfloat16* pl) {
    __nv_bfloat16 h = __float2bfloat16(v);
    *ph = h;
    *pl = __float2bfloat16(v - __bfloat162float(h));
}

// -------- prep: fused weight -> bf16 hi/lo; also zero scatter accumulators -----
__global__ void prep_weights(const float* __restrict__ W_fx, const float* __restrict__ b_fx,
                             const float* __restrict__ W_x, const float* __restrict__ b_x,
                             const float* __restrict__ W_slice, const float* __restrict__ b_slice) {
    int k = blockIdx.x;          // 0..255
    int t = threadIdx.x;         // 0..255
    // folded zeroing: g_st = 131072 floats -> every block zeroes 512 of them
    g_st[k * 512 + t] = 0.f;
    g_st[k * 512 + 256 + t] = 0.f;
    if (k < 8) g_sn[k * 256 + t] = 0.f;    // g_sn = 2048 floats

    for (int c = t; c < 512; c += 256)
        split_store(W_fx[k * 512 + c], &g_bWh[(size_t)c * 256 + k], &g_bWl[(size_t)c * 256 + k]);
    {
        int h = t >> 5, s = t & 31;
        float a = 0.f;
        #pragma unroll
        for (int d = 0; d < 64; d++)
            a += W_x[k * 512 + h * 64 + d] * W_slice[d * 32 + s];
        split_store(a, &g_bWh[(size_t)(512 + t) * 256 + k], &g_bWl[(size_t)(512 + t) * 256 + k]);
    }
    if (k == 0) {
        for (int c = t; c < 512; c += 256) g_bigb[c] = b_fx[c];
        int h = t >> 5, s = t & 31;
        float bb = b_slice[s];
        #pragma unroll
        for (int d = 0; d < 64; d++)
            bb += b_x[h * 64 + d] * W_slice[d * 32 + s];
        g_bigb[512 + t] = bb;
    }
}

// ---------------- pre-pass: x fp32 -> bf16 hi/lo (paid once, not 6x) -----------
__global__ void convert_x(const float* __restrict__ x, int total4) {
    int i = blockIdx.x * blockDim.x + threadIdx.x;
    if (i >= total4) return;
    float4 v = ((const float4*)x)[i];
    uint32_t h0, h1, l0, l1;
    split4(v, h0, h1, l0, l1);
    ((uint2*)g_xh)[i] = make_uint2(h0, h1);
    ((uint2*)g_xl)[i] = make_uint2(l0, l1);
}

// ========== split-bf16 HMMA fused GEMM: g_cat = x @ bigW + bias ===============
// Block tile 128x128, K=256 in 8 chunks of 32. 8 warps = 4(m) x 2(n), warp 32x64.
__global__ __launch_bounds__(256, 2) void fused_gemm_mma(int M) {
    __shared__ __align__(16) uint32_t Ahi[128 * PADK / 2];
    __shared__ __align__(16) uint32_t Alo[128 * PADK / 2];
    __shared__ __align__(16) uint32_t Bhi[128 * PADK / 2];
    __shared__ __align__(16) uint32_t Blo[128 * PADK / 2];

    int tid = threadIdx.x, wid = tid >> 5, lane = tid & 31;
    int bx = blockIdx.x, by = blockIdx.y;
    int row0 = by * 128, n0 = bx * 128;
    int warp_m = (wid & 3) * 32, warp_n = (wid >> 2) * 64;

    float acc[2][8][4];
    #pragma unroll
    for (int mi = 0; mi < 2; mi++)
        #pragma unroll
        for (int ni = 0; ni < 8; ni++)
            #pragma unroll
            for (int j = 0; j < 4; j++) acc[mi][ni][j] = 0.f;

    int a_row = ((lane >> 3) & 1) * 8 + (lane & 7);
    int a_col = (lane >> 4) * 8;
    int b_row = ((lane >> 4) & 1) * 8 + (lane & 7);
    int b_col = ((lane >> 3) & 1) * 8;

    uint32_t sAhi = smem_u32(Ahi), sAlo = smem_u32(Alo);
    uint32_t sBhi = smem_u32(Bhi), sBlo = smem_u32(Blo);

    int lrow = tid >> 1;                 // 0..127
    int lc0 = (tid & 1) * 16;            // 0 or 16

    for (int c = 0; c < 8; c++) {
        int k0 = c * 32;
        // ---- A chunk 128x32: direct bf16 hi/lo loads ----
        {
            int gr = row0 + lrow;
            uint32_t* dh = &Ahi[(lrow * PADK + lc0) >> 1];
            uint32_t* dl = &Alo[(lrow * PADK + lc0) >> 1];
            if (gr < M) {
                const uint4* sh = (const uint4*)&g_xh[(size_t)gr * 256 + k0 + lc0];
                const uint4* sl = (const uint4*)&g_xl[(size_t)gr * 256 + k0 + lc0];
                uint4 h0 = sh[0], h1 = sh[1], l0 = sl[0], l1 = sl[1];
                dh[0] = h0.x; dh[1] = h0.y; dh[2] = h0.z; dh[3] = h0.w;
                dh[4] = h1.x; dh[5] = h1.y; dh[6] = h1.z; dh[7] = h1.w;
                dl[0] = l0.x; dl[1] = l0.y; dl[2] = l0.z; dl[3] = l0.w;
                dl[4] = l1.x; dl[5] = l1.y; dl[6] = l1.z; dl[7] = l1.w;
            } else {
                #pragma unroll
                for (int i = 0; i < 8; i++) { dh[i] = 0u; dl[i] = 0u; }
            }
        }
        // ---- B chunk 128x32: direct bf16 hi/lo loads ----
        {
            const uint4* sh = (const uint4*)&g_bWh[(size_t)(n0 + lrow) * 256 + k0 + lc0];
            const uint4* sl = (const uint4*)&g_bWl[(size_t)(n0 + lrow) * 256 + k0 + lc0];
            uint32_t* dh = &Bhi[(lrow * PADK + lc0) >> 1];
            uint32_t* dl = &Blo[(lrow * PADK + lc0) >> 1];
            uint4 h0 = sh[0], h1 = sh[1], l0 = sl[0], l1 = sl[1];
            dh[0] = h0.x; dh[1] = h0.y; dh[2] = h0.z; dh[3] = h0.w;
            dh[4] = h1.x; dh[5] = h1.y; dh[6] = h1.z; dh[7] = h1.w;
            dl[0] = l0.x; dl[1] = l0.y; dl[2] = l0.z; dl[3] = l0.w;
            dl[4] = l1.x; dl[5] = l1.y; dl[6] = l1.z; dl[7] = l1.w;
        }
        __syncthreads();

        #pragma unroll
        for (int p = 0; p < 3; p++) {
            uint32_t sA = (p == 2) ? sAlo : sAhi;
            uint32_t sB = (p == 1) ? sBlo : sBhi;
            #pragma unroll
            for (int ks = 0; ks < 2; ks++) {
                int kb = ks * 16;
                uint32_t af[2][4];
                #pragma unroll
                for (int mi = 0; mi < 2; mi++)
                    ldsm_x4(af[mi], sA + ((warp_m + mi * 16 + a_row) * PADK + kb + a_col) * 2);
                uint32_t bfr[8][2];
                #pragma unroll
                for (int nj = 0; nj < 4; nj++) {
                    uint32_t r[4];
                    ldsm_x4(r, sB + ((warp_n + nj * 16 + b_row) * PADK + kb + b_col) * 2);
                    bfr[nj * 2][0] = r[0]; bfr[nj * 2][1] = r[1];
                    bfr[nj * 2 + 1][0] = r[2]; bfr[nj * 2 + 1][1] = r[3];
                }
                #pragma unroll
                for (int mi = 0; mi < 2; mi++)
                    #pragma unroll
                    for (int ni = 0; ni < 8; ni++)
                        mma_bf16(acc[mi][ni], af[mi], bfr[ni]);
            }
        }
        __syncthreads();
    }

    // ---- epilogue: add bias, store fp32 to g_cat ----
    int r_in = lane >> 2, c_in = (lane & 3) * 2;
    #pragma unroll
    for (int mi = 0; mi < 2; mi++) {
        #pragma unroll
        for (int ni = 0; ni < 8; ni++) {
            int gc = n0 + warp_n + ni * 8 + c_in;
            float b0 = g_bigb[gc], b1 = g_bigb[gc + 1];
            int gr0 = row0 + warp_m + mi * 16 + r_in;
            if (gr0 < M) {
                float2 o = make_float2(acc[mi][ni][0] + b0, acc[mi][ni][1] + b1);
                *(float2*)&g_cat[(size_t)gr0 * 768 + gc] = o;
            }
            int gr1 = gr0 + 8;
            if (gr1 < M) {
                float2 o = make_float2(acc[mi][ni][2] + b0, acc[mi][ni][3] + b1);
                *(float2*)&g_cat[(size_t)gr1 * 768 + gc] = o;
            }
        }
    }
}

// --------- tempered softmax over S=32; fp32 in place + bf16 hi/lo out ----------
__global__ void softmax_kernel(const float* __restrict__ temp, int total) {
    int gw = blockIdx.x * 8 + (threadIdx.x >> 5);
    int lane = threadIdx.x & 31;
    if (gw >= total) return;
    int n = gw >> 3, h = gw & 7;
    float* p = &g_cat[(size_t)n * 768 + 512 + h * 32 + lane];
    float v = *p / temp[h];
    float m = v;
    #pragma unroll
    for (int o = 16; o; o >>= 1) m = fmaxf(m, __shfl_xor_sync(0xffffffffu, m, o));
    float e = __expf(v - m);
    float s = e;
    #pragma unroll
    for (int o = 16; o; o >>= 1) s += __shfl_xor_sync(0xffffffffu, s, o);
    float r = e / s;
    *p = r;
    size_t idx = (size_t)n * 256 + h * 32 + lane;
    split_store(r, &g_wh[idx], &g_wl[idx]);
}

// ------ scatter: warp-per-(chunk,head); 2 warps/block, grid (chunks, 4) --------
// 4x the blocks of the old layout -> latency-bound loop gets hidden.
__global__ void scatter_kernel(const int* __restrict__ batch, int N) {
    int h = blockIdx.y * 2 + (threadIdx.x >> 5);   // head 0..7
    int lane = threadIdx.x & 31;                   // slice
    int start = blockIdx.x * CHUNK;
    int end = min(start + CHUNK, N);

    float acc[64];
    #pragma unroll
    for (int d = 0; d < 64; d++) acc[d] = 0.f;
    float accn = 0.f;
    int cur_b = __ldg(&batch[start]);

    for (int n = start; n < end; n++) {
        int bn = __ldg(&batch[n]);
        if (bn != cur_b) {
            float* st = g_st + (((size_t)cur_b * 8 + h) * 32 + lane) * 64;
            #pragma unroll
            for (int d = 0; d < 64; d++) { atomicAdd(&st[d], acc[d]); acc[d] = 0.f; }
            atomicAdd(&g_sn[(cur_b * 8 + h) * 32 + lane], accn);
            accn = 0.f;
            cur_b = bn;
        }
        const float* row = &g_cat[(size_t)n * 768];
        float wv = row[512 + h * 32 + lane];
        float f0 = row[h * 64 + lane];
        float f1 = row[h * 64 + 32 + lane];
        accn += wv;
        #pragma unroll
        for (int d = 0; d < 32; d++) {
            acc[d]      += wv * __shfl_sync(0xffffffffu, f0, d);
            acc[d + 32] += wv * __shfl_sync(0xffffffffu, f1, d);
        }
    }
    float* st = g_st + (((size_t)cur_b * 8 + h) * 32 + lane) * 64;
    #pragma unroll
    for (int d = 0; d < 64; d++) atomicAdd(&st[d], acc[d]);
    atomicAdd(&g_sn[(cur_b * 8 + h) * 32 + lane], accn);
}

// ---------------- tiny attention over slice tokens, one block per (b,h) --------
__global__ void attention_kernel(const float* __restrict__ W_q, const float* __restrict__ W_k,
                                 const float* __restrict__ W_v) {
    int bh = blockIdx.x;
    __shared__ float st[32 * 64];
    __shared__ float q[32 * 64];
    __shared__ float kT[64 * 33];
    __shared__ float v[32 * 64];
    __shared__ float attn[32 * 32];
    int tid = threadIdx.x;
    const float* base = g_st + (size_t)bh * 2048;
    const float* nrm = g_sn + bh * 32;

    for (int i = tid; i < 2048; i += 256) {
        int s = i >> 6;
        st[i] = base[i] / (nrm[s] + 1e-5f);
    }
    __syncthreads();
    for (int i = tid; i < 2048; i += 256) {
        int s = i >> 6, e = i & 63;
        float aq = 0.f, ak = 0.f, av = 0.f;
        #pragma unroll
        for (int d = 0; d < 64; d++) {
            float sv = st[s * 64 + d];
            aq += sv * W_q[d * 64 + e];
            ak += sv * W_k[d * 64 + e];
            av += sv * W_v[d * 64 + e];
        }
        q[i] = aq; kT[e * 33 + s] = ak; v[i] = av;
    }
    __syncthreads();
    for (int i = tid; i < 1024; i += 256) {
        int s = i >> 5, t = i & 31;
        float a = 0.f;
        #pragma unroll
        for (int d = 0; d < 64; d++) a += q[s * 64 + d] * kT[d * 33 + t];
        attn[i] = a * 0.125f;
    }
    __syncthreads();
    int warp = tid >> 5, lane = tid & 31;
    for (int r = warp; r < 32; r += 8) {
        float val = attn[r * 32 + lane];
        float m = val;
        #pragma unroll
        for (int o = 16; o; o >>= 1) m = fmaxf(m, __shfl_xor_sync(0xffffffffu, m, o));
        float e = __expf(val - m);
        float ssum = e;
        #pragma unroll
        for (int o = 16; o; o >>= 1) ssum += __shfl_xor_sync(0xffffffffu, ssum, o);
        attn[r * 32 + lane] = e / ssum;
    }
    __syncthreads();
    float* ob = g_ot + (size_t)bh * 2048;
    for (int i = tid; i < 2048; i += 256) {
        int s = i >> 6, d = i & 63;
        float a = 0.f;
        #pragma unroll
        for (int t = 0; t < 32; t++) a += attn[s * 32 + t] * v[t * 64 + d];
        ob[i] = a;
    }
}

// --------- fold out_tok with W_out -> M1 TRANSPOSED bf16 hi/lo [b][j][hs] ------
__global__ void build_m1(const float* __restrict__ W_out) {
    int bh = blockIdx.x;
    int h = bh & 7, b = bh >> 3;
    __shared__ float ot[2048];
    int tid = threadIdx.x;
    for (int i = tid; i < 2048; i += 256) ot[i] = g_ot[(size_t)bh * 2048 + i];
    __syncthreads();
    for (int i = tid; i < 8192; i += 256) {
        int s = i >> 8, j = i & 255;
        float a = 0.f;
        #pragma unroll
        for (int d = 0; d < 64; d++)
            a += ot[s * 64 + d] * W_out[(h * 64 + d) * 256 + j];
        size_t idx = ((size_t)b * 256 + j) * 256 + (h * 32 + s);
        split_store(a, &g_m1h[idx], &g_m1l[idx]);
    }
}

// ===== final: out[n,:] = w[n,:] @ M1[batch[n]] + b_out (split-bf16 HMMA) ======
__global__ __launch_bounds__(256, 2) void final_gemm_mma(
    int M, const int* __restrict__ batch,
    const float* __restrict__ bias, float* __restrict__ C)
{
    __shared__ __align__(16) uint32_t Ahi[128 * PADK / 2];
    __shared__ __align__(16) uint32_t Alo[128 * PADK / 2];
    __shared__ __align__(16) uint32_t Bhi[128 * PADK / 2];
    __shared__ __align__(16) uint32_t Blo[128 * PADK / 2];
    __shared__ int sb[128];

    int tid = threadIdx.x, wid = tid >> 5, lane = tid & 31;
    int bx = blockIdx.x, by = blockIdx.y;
    int row0 = by * 128, n0 = bx * 128;
    int rows = min(128, M - row0);
    int warp_m = (wid & 3) * 32, warp_n = (wid >> 2) * 64;

    for (int i = tid; i < 128; i += 256) sb[i] = (i < rows) ? batch[row0 + i] : -1;
    __syncthreads();
    int b_first = sb[0], b_last = sb[rows - 1];

    int a_row = ((lane >> 3) & 1) * 8 + (lane & 7);
    int a_col = (lane >> 4) * 8;
    int b_row = ((lane >> 4) & 1) * 8 + (lane & 7);
    int b_col = ((lane >> 3) & 1) * 8;

    uint32_t sAhi = smem_u32(Ahi), sAlo = smem_u32(Alo);
    uint32_t sBhi = smem_u32(Bhi), sBlo = smem_u32(Blo);

    int lrow = tid >> 1;
    int lc0 = (tid & 1) * 16;
    int r_in = lane >> 2, c_in = (lane & 3) * 2;

    for (int bb = b_first; bb <= b_last; bb++) {
        float acc[2][8][4];
        #pragma unroll
        for (int mi = 0; mi < 2; mi++)
            #pragma unroll
            for (int ni = 0; ni < 8; ni++)
                #pragma unroll
                for (int j = 0; j < 4; j++) acc[mi][ni][j] = 0.f;

        const __nv_bfloat16* Bh = g_m1h + (size_t)bb * 65536;
        const __nv_bfloat16* Bl = g_m1l + (size_t)bb * 65536;

        for (int c = 0; c < 8; c++) {
            int k0 = c * 32;
            // ---- A chunk: w bf16 hi/lo [128 x 32] ----
            {
                int gr = row0 + lrow;
                uint32_t* dh = &Ahi[(lrow * PADK + lc0) >> 1];
                uint32_t* dl = &Alo[(lrow * PADK + lc0) >> 1];
                if (gr < M) {
                    const uint4* sh = (const uint4*)&g_wh[(size_t)gr * 256 + k0 + lc0];
                    const uint4* sl = (const uint4*)&g_wl[(size_t)gr * 256 + k0 + lc0];
                    uint4 h0 = sh[0], h1 = sh[1], l0 = sl[0], l1 = sl[1];
                    dh[0] = h0.x; dh[1] = h0.y; dh[2] = h0.z; dh[3] = h0.w;
                    dh[4] = h1.x; dh[5] = h1.y; dh[6] = h1.z; dh[7] = h1.w;
                    dl[0] = l0.x; dl[1] = l0.y; dl[2] = l0.z; dl[3] = l0.w;
                    dl[4] = l1.x; dl[5] = l1.y; dl[6] = l1.z; dl[7] = l1.w;
                } else {
                    #pragma unroll
                    for (int i = 0; i < 8; i++) { dh[i] = 0u; dl[i] = 0u; }
                }
            }
            // ---- B chunk: M1t bf16 hi/lo [128 x 32] ----
            {
                const uint4* sh = (const uint4*)&Bh[(size_t)(n0 + lrow) * 256 + k0 + lc0];
                const uint4* sl = (const uint4*)&Bl[(size_t)(n0 + lrow) * 256 + k0 + lc0];
                uint32_t* dh = &Bhi[(lrow * PADK + lc0) >> 1];
                uint32_t* dl = &Blo[(lrow * PADK + lc0) >> 1];
                uint4 h0 = sh[0], h1 = sh[1], l0 = sl[0], l1 = sl[1];
                dh[0] = h0.x; dh[1] = h0.y; dh[2] = h0.z; dh[3] = h0.w;
                dh[4] = h1.x; dh[5] = h1.y; dh[6] = h1.z; dh[7] = h1.w;
                dl[0] = l0.x; dl[1] = l0.y; dl[2] = l0.z; dl[3] = l0.w;
                dl[4] = l1.x; dl[5] = l1.y; dl[6] = l1.z; dl[7] = l1.w;
            }
            __syncthreads();

            #pragma unroll
            for (int p = 0; p < 3; p++) {
                uint32_t sA = (p == 2) ? sAlo : sAhi;
                uint32_t sB = (p == 1) ? sBlo : sBhi;
                #pragma unroll
                for (int ks = 0; ks < 2; ks++) {
                    int kb = ks * 16;
                    uint32_t af[2][4];
                    #pragma unroll
                    for (int mi = 0; mi < 2; mi++)
                        ldsm_x4(af[mi], sA + ((warp_m + mi * 16 + a_row) * PADK + kb + a_col) * 2);
                    uint32_t bfr[8][2];
                    #pragma unroll
                    for (int nj = 0; nj < 4; nj++) {
                        uint32_t r[4];
                        ldsm_x4(r, sB + ((warp_n + nj * 16 + b_row) * PADK + kb + b_col) * 2);
                        bfr[nj * 2][0] = r[0]; bfr[nj * 2][1] = r[1];
                        bfr[nj * 2 + 1][0] = r[2]; bfr[nj * 2 + 1][1] = r[3];
                    }
                    #pragma unroll
                    for (int mi = 0; mi < 2; mi++)
                        #pragma unroll
                        for (int ni = 0; ni < 8; ni++)
                            mma_bf16(acc[mi][ni], af[mi], bfr[ni]);
                }
            }
            __syncthreads();
        }

        // ---- epilogue: rows belonging to bb only ----
        #pragma unroll
        for (int mi = 0; mi < 2; mi++) {
            #pragma unroll
            for (int ni = 0; ni < 8; ni++) {
                int gc = n0 + warp_n + ni * 8 + c_in;
                float b0 = bias[gc], b1 = bias[gc + 1];
                int lr0 = warp_m + mi * 16 + r_in;
                int gr0 = row0 + lr0;
                if (gr0 < M && sb[lr0] == bb) {
                    float2 o = make_float2(acc[mi][ni][0] + b0, acc[mi][ni][1] + b1);
                    *(float2*)&C[(size_t)gr0 * 256 + gc] = o;
                }
                int lr1 = lr0 + 8;
                int gr1 = gr0 + 8;
                if (gr1 < M && sb[lr1] == bb) {
                    float2 o = make_float2(acc[mi][ni][2] + b0, acc[mi][ni][3] + b1);
                    *(float2*)&C[(size_t)gr1 * 256 + gc] = o;
                }
            }
        }
    }
}

// ---------------- launch ----------------
extern "C" void kernel_launch(void* const* d_in, const int* in_sizes, int n_in,
                              void* d_out, int out_size) {
    const float* x       = (const float*)d_in[0];
    const int*   batch   = (const int*)d_in[1];
    const float* W_fx    = (const float*)d_in[2];
    const float* b_fx    = (const float*)d_in[3];
    const float* W_x     = (const float*)d_in[4];
    const float* b_x     = (const float*)d_in[5];
    const float* W_slice = (const float*)d_in[6];
    const float* b_slice = (const float*)d_in[7];
    const float* gtemp   = (const float*)d_in[8];
    const float* W_q     = (const float*)d_in[9];
    const float* W_k     = (const float*)d_in[10];
    const float* W_v     = (const float*)d_in[11];
    const float* W_out   = (const float*)d_in[12];
    const float* b_out   = (const float*)d_in[13];
    float* out = (float*)d_out;

    int n = in_sizes[1];
    int rowBlocks = (n + 127) / 128;

    // 1. build fused weight bf16 hi/lo + bias; zero accumulators (full)
    prep_weights<<<256, 256>>>(W_fx, b_fx, W_x, b_x, W_slice, b_slice);
    // 2. pre-convert x to bf16 hi/lo (once)
    convert_x<<<(n * 64 + 255) / 256, 256>>>(x, n * 64);
    // 3. split-bf16 HMMA fused GEMM: [fx | logits] = x @ bigW + bigb
    fused_gemm_mma<<<dim3(6, rowBlocks), 256>>>(n);
    // 4. tempered softmax (standalone, grid-parallel; emits fp32 + bf16 w)
    softmax_kernel<<<n, 256>>>(gtemp, n * 8);
    // 5. scatter-add pooling: warp-per-(chunk,head), 4x block parallelism
    scatter_kernel<<<dim3(rowBlocks, 4), 64>>>(batch, n);
    // 6. tiny attention over slice tokens
    attention_kernel<<<64, 256>>>(W_q, W_k, W_v);
    // 7. fold out_tok with W_out -> transposed bf16 hi/lo M1
    build_m1<<<64, 256>>>(W_out);
    // 8. out = w @ M1[batch] + b_out   (split-bf16 HMMA)
    final_gemm_mma<<<dim3(2, rowBlocks), 256>>>(n, batch, b_out, out);
}